// round 1
// baseline (speedup 1.0000x reference)
#include <cuda_runtime.h>
#include <cstdint>

// Problem constants
#define NNODES 4096       // B*N = 8*512
#define KNBR   16
#define CPOOL  256
#define GDIM   128
#define INDIM  384        // CPOOL + GDIM
#define LDIM   512
#define OUTLD  1920       // 384 + 3*512

// ---------------- device scratch (no allocations allowed) ----------------
__device__ float g_H   [NNODES * GDIM];      // geo hidden
__device__ float g_X0  [NNODES * INDIM];     // layer-0 node features
__device__ float g_X   [NNODES * LDIM];      // current node features (layers 1..)
__device__ float g_D   [NNODES * 1024];      // [A | C] per node
__device__ float g_Wcat[1024 * LDIM];        // stacked [W_l ; W_r - W_l]
__device__ float g_biasL[1024];              // [0...0, fcb]

// ---------------- generic tiled SGEMM: C = A(MxK) * B(NxK)^T + bias -------
// A row-major lda, B row-major ldb, C row-major ldc with column offset c_off.
#define TM 64
#define TN 64
#define TK 16

__global__ void sgemm_tn(const float* __restrict__ A, int lda,
                         const float* __restrict__ B, int ldb,
                         const float* __restrict__ bias,
                         float* __restrict__ C, int ldc, int c_off,
                         int M, int N, int K, int do_relu)
{
    __shared__ float As[TK][TM];
    __shared__ float Bs[TK][TN];

    const int bm = blockIdx.y * TM;
    const int bn = blockIdx.x * TN;
    const int tx = threadIdx.x;      // 0..15
    const int ty = threadIdx.y;      // 0..15
    const int tid = ty * 16 + tx;

    float acc[4][4] = {};

    for (int k0 = 0; k0 < K; k0 += TK) {
        // load A tile (TM x TK) into As[k][m]
        #pragma unroll
        for (int i = tid; i < TM * TK; i += 256) {
            int m = i / TK, k = i % TK;
            float v = 0.0f;
            int gm = bm + m, gk = k0 + k;
            if (gm < M && gk < K) v = A[(size_t)gm * lda + gk];
            As[k][m] = v;
        }
        // load B tile (TN x TK) into Bs[k][n]
        #pragma unroll
        for (int i = tid; i < TN * TK; i += 256) {
            int n = i / TK, k = i % TK;
            float v = 0.0f;
            int gn = bn + n, gk = k0 + k;
            if (gn < N && gk < K) v = B[(size_t)gn * ldb + gk];
            Bs[k][n] = v;
        }
        __syncthreads();

        #pragma unroll
        for (int kk = 0; kk < TK; kk++) {
            float4 av = *reinterpret_cast<const float4*>(&As[kk][ty * 4]);
            float4 bv = *reinterpret_cast<const float4*>(&Bs[kk][tx * 4]);
            float a[4] = {av.x, av.y, av.z, av.w};
            float b[4] = {bv.x, bv.y, bv.z, bv.w};
            #pragma unroll
            for (int i = 0; i < 4; i++)
                #pragma unroll
                for (int j = 0; j < 4; j++)
                    acc[i][j] = fmaf(a[i], b[j], acc[i][j]);
        }
        __syncthreads();
    }

    #pragma unroll
    for (int i = 0; i < 4; i++) {
        int m = bm + ty * 4 + i;
        if (m >= M) continue;
        #pragma unroll
        for (int j = 0; j < 4; j++) {
            int n = bn + tx * 4 + j;
            if (n >= N) continue;
            float v = acc[i][j];
            if (bias) v += bias[n];
            if (do_relu) v = fmaxf(v, 0.0f);
            C[(size_t)m * ldc + c_off + n] = v;
        }
    }
}

// ---------------- weight prep: Wcat = [W_l ; W_r - W_l], biasL = [0 ; b] ---
__global__ void prep_w(const float* __restrict__ W,  // 512 x (2*Kin)
                       const float* __restrict__ b,  // 512
                       int Kin,
                       float* __restrict__ Wcat,     // 1024 x Kin
                       float* __restrict__ biasL)    // 1024
{
    int idx = blockIdx.x * blockDim.x + threadIdx.x;
    int total = 512 * Kin;
    if (idx < total) {
        int r = idx / Kin, c = idx % Kin;
        float wl = W[(size_t)r * 2 * Kin + c];
        float wr = W[(size_t)r * 2 * Kin + Kin + c];
        Wcat[(size_t)r * Kin + c]          = wl;
        Wcat[(size_t)(512 + r) * Kin + c]  = wr - wl;
    }
    if (idx < 512) {
        biasL[idx]        = 0.0f;
        biasL[512 + idx]  = b[idx];
    }
}

// ---------------- copy pooled features into X0[:, 0:256] ------------------
__global__ void copy_pool(const float* __restrict__ pooled, float* __restrict__ X0)
{
    int idx = blockIdx.x * blockDim.x + threadIdx.x;
    if (idx < NNODES * CPOOL) {
        int n = idx >> 8;          // /256
        int c = idx & 255;
        X0[(size_t)n * INDIM + c] = pooled[idx];
    }
}

// ---------------- copy X0 into out[:, 0:384] -------------------------------
__global__ void copy_x0_out(const float* __restrict__ X0, float* __restrict__ out)
{
    int idx = blockIdx.x * blockDim.x + threadIdx.x;
    if (idx < NNODES * INDIM) {
        int n = idx / INDIM;
        int c = idx - n * INDIM;
        out[(size_t)n * OUTLD + c] = X0[idx];
    }
}

// ---------------- edge aggregation: x_new[n] = max_k relu(A[src_k]+C[n]) ---
// D layout per node: cols [0,512) = A, cols [512,1024) = C (bias included).
// One block per node, 128 threads, 4 floats each (float4).
__global__ void aggregate(const float* __restrict__ D,
                          const int*   __restrict__ src,
                          float* __restrict__ Xn,    // 4096 x 512
                          float* __restrict__ out,   // 4096 x 1920
                          int out_off)
{
    const int n  = blockIdx.x;
    const int f4 = threadIdx.x;   // 0..127

    float4 c = *reinterpret_cast<const float4*>(D + (size_t)n * 1024 + 512 + f4 * 4);
    float4 m = make_float4(0.f, 0.f, 0.f, 0.f);   // relu floor

    #pragma unroll
    for (int k = 0; k < KNBR; k++) {
        int j = src[n * KNBR + k];
        float4 a = *reinterpret_cast<const float4*>(D + (size_t)j * 1024 + f4 * 4);
        m.x = fmaxf(m.x, a.x + c.x);
        m.y = fmaxf(m.y, a.y + c.y);
        m.z = fmaxf(m.z, a.z + c.z);
        m.w = fmaxf(m.w, a.w + c.w);
    }
    *reinterpret_cast<float4*>(Xn  + (size_t)n * LDIM  + f4 * 4) = m;
    *reinterpret_cast<float4*>(out + (size_t)n * OUTLD + out_off + f4 * 4) = m;
}

// ---------------------------------------------------------------------------
extern "C" void kernel_launch(void* const* d_in, const int* in_sizes, int n_in,
                              void* d_out, int out_size)
{
    const float* rois   = (const float*)d_in[0];
    const float* pooled = (const float*)d_in[1];
    const int*   edge   = (const int*)  d_in[2];   // (2, 65536): row 0 = src
    const float* gW1    = (const float*)d_in[3];
    const float* gb1    = (const float*)d_in[4];
    const float* gW2    = (const float*)d_in[5];
    const float* gb2    = (const float*)d_in[6];
    const float* fcW[3] = {(const float*)d_in[7], (const float*)d_in[9],  (const float*)d_in[11]};
    const float* fcb[3] = {(const float*)d_in[8], (const float*)d_in[10], (const float*)d_in[12]};
    float* out = (float*)d_out;

    const int* src = edge;  // first 65536 entries

    float *H, *X0, *X, *D, *Wcat, *biasL;
    cudaGetSymbolAddress((void**)&H,     g_H);
    cudaGetSymbolAddress((void**)&X0,    g_X0);
    cudaGetSymbolAddress((void**)&X,     g_X);
    cudaGetSymbolAddress((void**)&D,     g_D);
    cudaGetSymbolAddress((void**)&Wcat,  g_Wcat);
    cudaGetSymbolAddress((void**)&biasL, g_biasL);

    dim3 blk(16, 16);

    // 1) geo MLP layer 1: H = relu(rois @ gW1.T + gb1)   (4096x7 @ 7x128)
    sgemm_tn<<<dim3(GDIM / TN, NNODES / TM), blk>>>(
        rois, 7, gW1, 7, gb1, H, GDIM, 0, NNODES, GDIM, 7, 1);

    // 2) geo MLP layer 2: X0[:,256:384] = relu(H @ gW2.T + gb2)
    sgemm_tn<<<dim3(GDIM / TN, NNODES / TM), blk>>>(
        H, GDIM, gW2, GDIM, gb2, X0, INDIM, CPOOL, NNODES, GDIM, GDIM, 1);

    // 3) X0[:,0:256] = pooled
    copy_pool<<<(NNODES * CPOOL + 255) / 256, 256>>>(pooled, X0);

    // 4) out[:,0:384] = X0
    copy_x0_out<<<(NNODES * INDIM + 255) / 256, 256>>>(X0, out);

    // 5) three EdgeConv layers
    const int Kin[3]    = {INDIM, LDIM, LDIM};
    const int outOff[3] = {384, 384 + 512, 384 + 1024};

    for (int l = 0; l < 3; l++) {
        int k = Kin[l];

        // 5a) stacked weights + bias
        prep_w<<<(512 * k + 255) / 256, 256>>>(fcW[l], fcb[l], k, Wcat, biasL);

        // 5b) D = X_l @ Wcat.T + biasL   (4096 x 1024, K=k)
        const float* Xin  = (l == 0) ? X0 : X;
        int          ldx  = (l == 0) ? INDIM : LDIM;
        sgemm_tn<<<dim3(1024 / TN, NNODES / TM), blk>>>(
            Xin, ldx, Wcat, k, biasL, D, 1024, 0, NNODES, 1024, k, 0);

        // 5c) aggregate: X_{l+1}[n] = max_k relu(A[src]+C[n]); also write out
        aggregate<<<NNODES, 128>>>(D, src, X, out, outOff[l]);
    }
}

// round 2
// speedup vs baseline: 2.2380x; 2.2380x over previous
#include <cuda_runtime.h>
#include <cstdint>

// Problem constants
#define NNODES 4096       // B*N = 8*512
#define KNBR   16
#define CPOOL  256
#define GDIM   128
#define INDIM  384        // CPOOL + GDIM
#define LDIM   512
#define OUTLD  1920       // 384 + 3*512

// ---------------- device scratch (no allocations allowed) ----------------
__device__ float g_H   [NNODES * GDIM];      // geo hidden
__device__ float g_X0  [NNODES * INDIM];     // layer-0 node features
__device__ float g_X   [NNODES * LDIM];      // current node features
__device__ float g_D   [NNODES * 1024];      // [A | C] per node
__device__ float g_Wcat[1024 * LDIM];        // stacked [W_l ; W_r - W_l]
__device__ float g_biasL[1024];              // [0...0, fcb]

// =====================================================================
// Fast SGEMM with packed f32x2 FMAs.
// C(M x N) = A(M x K) @ B(N x K)^T + bias, optional relu.
// Requires: M % 128 == 0, N % 64 == 0, K % 16 == 0.
// Tile: BM=128, BN=64, BK=16. 256 threads. Per thread: 8(M) x 4(N),
// accumulators are f32x2 packed along M (row pairs).
// =====================================================================
#define BM 128
#define BN 64
#define BK 16

__global__ __launch_bounds__(256) void sgemm_f2(
    const float* __restrict__ A, int lda,
    const float* __restrict__ B, int ldb,
    const float* __restrict__ bias,
    float* __restrict__ C, int ldc, int c_off,
    int K, int do_relu)
{
    __shared__ float As[2][BK][BM];   // 2 * 8KB
    __shared__ float Bs[2][BK][BN];   // 2 * 4KB

    const int tid = threadIdx.x;
    const int tx  = tid & 15;         // N group: 4 cols
    const int ty  = tid >> 4;         // M group: 8 rows
    const int bm  = blockIdx.y * BM;
    const int bn  = blockIdx.x * BN;

    // gmem load mapping
    const int am  = tid >> 1;             // 0..127 : A row within tile
    const int ak  = (tid & 1) * 8;        // 0 or 8 : A k-offset (8 wide)
    const int bnr = tid >> 2;             // 0..63  : B row within tile
    const int bk  = (tid & 3) * 4;        // 0,4,8,12 : B k-offset (4 wide)

    const float* Aptr = A + (size_t)(bm + am) * lda + ak;
    const float* Bptr = B + (size_t)(bn + bnr) * ldb + bk;

    // prologue: tile 0 -> regs -> smem buf 0
    float4 ra0 = *(const float4*)(Aptr);
    float4 ra1 = *(const float4*)(Aptr + 4);
    float4 rb  = *(const float4*)(Bptr);

    As[0][ak + 0][am] = ra0.x;  As[0][ak + 1][am] = ra0.y;
    As[0][ak + 2][am] = ra0.z;  As[0][ak + 3][am] = ra0.w;
    As[0][ak + 4][am] = ra1.x;  As[0][ak + 5][am] = ra1.y;
    As[0][ak + 6][am] = ra1.z;  As[0][ak + 7][am] = ra1.w;
    Bs[0][bk + 0][bnr] = rb.x;  Bs[0][bk + 1][bnr] = rb.y;
    Bs[0][bk + 2][bnr] = rb.z;  Bs[0][bk + 3][bnr] = rb.w;

    unsigned long long acc[4][4];
    #pragma unroll
    for (int i = 0; i < 4; i++)
        #pragma unroll
        for (int j = 0; j < 4; j++)
            acc[i][j] = 0ull;

    const int nk = K / BK;
    int buf = 0;
    __syncthreads();

    for (int kt = 0; kt < nk; kt++) {
        const bool has_next = (kt + 1 < nk);
        if (has_next) {
            const float* Ap = Aptr + (kt + 1) * BK;
            ra0 = *(const float4*)(Ap);
            ra1 = *(const float4*)(Ap + 4);
            rb  = *(const float4*)(Bptr + (kt + 1) * BK);
        }

        #pragma unroll
        for (int kk = 0; kk < BK; kk++) {
            // A fragment: 8 rows = 4 naturally-packed f32x2 (row pairs)
            ulonglong2 av0 = *(const ulonglong2*)&As[buf][kk][ty * 8];
            ulonglong2 av1 = *(const ulonglong2*)&As[buf][kk][ty * 8 + 4];
            unsigned long long a0 = av0.x, a1 = av0.y, a2 = av1.x, a3 = av1.y;

            // B fragment: 4 scalars, duplicated into both f32x2 halves
            float4 bq = *(const float4*)&Bs[buf][kk][tx * 4];
            unsigned long long b0, b1, b2, b3;
            asm("mov.b64 %0, {%1, %1};" : "=l"(b0) : "f"(bq.x));
            asm("mov.b64 %0, {%1, %1};" : "=l"(b1) : "f"(bq.y));
            asm("mov.b64 %0, {%1, %1};" : "=l"(b2) : "f"(bq.z));
            asm("mov.b64 %0, {%1, %1};" : "=l"(b3) : "f"(bq.w));

            #define FF2(d, a, b) \
                asm("fma.rn.f32x2 %0, %1, %2, %0;" : "+l"(d) : "l"(a), "l"(b))
            FF2(acc[0][0], a0, b0); FF2(acc[0][1], a0, b1);
            FF2(acc[0][2], a0, b2); FF2(acc[0][3], a0, b3);
            FF2(acc[1][0], a1, b0); FF2(acc[1][1], a1, b1);
            FF2(acc[1][2], a1, b2); FF2(acc[1][3], a1, b3);
            FF2(acc[2][0], a2, b0); FF2(acc[2][1], a2, b1);
            FF2(acc[2][2], a2, b2); FF2(acc[2][3], a2, b3);
            FF2(acc[3][0], a3, b0); FF2(acc[3][1], a3, b1);
            FF2(acc[3][2], a3, b2); FF2(acc[3][3], a3, b3);
            #undef FF2
        }

        if (has_next) {
            const int nb = buf ^ 1;
            As[nb][ak + 0][am] = ra0.x;  As[nb][ak + 1][am] = ra0.y;
            As[nb][ak + 2][am] = ra0.z;  As[nb][ak + 3][am] = ra0.w;
            As[nb][ak + 4][am] = ra1.x;  As[nb][ak + 5][am] = ra1.y;
            As[nb][ak + 6][am] = ra1.z;  As[nb][ak + 7][am] = ra1.w;
            Bs[nb][bk + 0][bnr] = rb.x;  Bs[nb][bk + 1][bnr] = rb.y;
            Bs[nb][bk + 2][bnr] = rb.z;  Bs[nb][bk + 3][bnr] = rb.w;
            __syncthreads();
            buf = nb;
        }
    }

    // epilogue
    #pragma unroll
    for (int mp = 0; mp < 4; mp++) {
        const int r0 = bm + ty * 8 + mp * 2;
        #pragma unroll
        for (int j = 0; j < 4; j++) {
            const int n = bn + tx * 4 + j;
            float lo, hi;
            asm("mov.b64 {%0, %1}, %2;" : "=f"(lo), "=f"(hi) : "l"(acc[mp][j]));
            float bv = bias ? bias[n] : 0.0f;
            lo += bv; hi += bv;
            if (do_relu) { lo = fmaxf(lo, 0.0f); hi = fmaxf(hi, 0.0f); }
            C[(size_t)r0 * ldc + c_off + n]       = lo;
            C[(size_t)(r0 + 1) * ldc + c_off + n] = hi;
        }
    }
}

// ---------------- generic tiled SGEMM (fallback, used for K=7 layer) ------
#define TM 64
#define TN 64
#define TK 16

__global__ void sgemm_tn(const float* __restrict__ A, int lda,
                         const float* __restrict__ B, int ldb,
                         const float* __restrict__ bias,
                         float* __restrict__ C, int ldc, int c_off,
                         int M, int N, int K, int do_relu)
{
    __shared__ float Ams[TK][TM];
    __shared__ float Bms[TK][TN];

    const int bm = blockIdx.y * TM;
    const int bn = blockIdx.x * TN;
    const int tx = threadIdx.x;
    const int ty = threadIdx.y;
    const int tid = ty * 16 + tx;

    float acc[4][4] = {};

    for (int k0 = 0; k0 < K; k0 += TK) {
        #pragma unroll
        for (int i = tid; i < TM * TK; i += 256) {
            int m = i / TK, k = i % TK;
            float v = 0.0f;
            int gm = bm + m, gk = k0 + k;
            if (gm < M && gk < K) v = A[(size_t)gm * lda + gk];
            Ams[k][m] = v;
        }
        #pragma unroll
        for (int i = tid; i < TN * TK; i += 256) {
            int n = i / TK, k = i % TK;
            float v = 0.0f;
            int gn = bn + n, gk = k0 + k;
            if (gn < N && gk < K) v = B[(size_t)gn * ldb + gk];
            Bms[k][n] = v;
        }
        __syncthreads();

        #pragma unroll
        for (int kk = 0; kk < TK; kk++) {
            float4 av = *reinterpret_cast<const float4*>(&Ams[kk][ty * 4]);
            float4 bv = *reinterpret_cast<const float4*>(&Bms[kk][tx * 4]);
            float a[4] = {av.x, av.y, av.z, av.w};
            float b[4] = {bv.x, bv.y, bv.z, bv.w};
            #pragma unroll
            for (int i = 0; i < 4; i++)
                #pragma unroll
                for (int j = 0; j < 4; j++)
                    acc[i][j] = fmaf(a[i], b[j], acc[i][j]);
        }
        __syncthreads();
    }

    #pragma unroll
    for (int i = 0; i < 4; i++) {
        int m = bm + ty * 4 + i;
        if (m >= M) continue;
        #pragma unroll
        for (int j = 0; j < 4; j++) {
            int n = bn + tx * 4 + j;
            if (n >= N) continue;
            float v = acc[i][j];
            if (bias) v += bias[n];
            if (do_relu) v = fmaxf(v, 0.0f);
            C[(size_t)m * ldc + c_off + n] = v;
        }
    }
}

// ---------------- weight prep: Wcat = [W_l ; W_r - W_l], biasL = [0 ; b] ---
__global__ void prep_w(const float* __restrict__ W,  // 512 x (2*Kin)
                       const float* __restrict__ b,  // 512
                       int Kin,
                       float* __restrict__ Wcat,     // 1024 x Kin
                       float* __restrict__ biasL)    // 1024
{
    int idx = blockIdx.x * blockDim.x + threadIdx.x;
    int total = 512 * Kin;
    if (idx < total) {
        int r = idx / Kin, c = idx % Kin;
        float wl = W[(size_t)r * 2 * Kin + c];
        float wr = W[(size_t)r * 2 * Kin + Kin + c];
        Wcat[(size_t)r * Kin + c]          = wl;
        Wcat[(size_t)(512 + r) * Kin + c]  = wr - wl;
    }
    if (idx < 512) {
        biasL[idx]        = 0.0f;
        biasL[512 + idx]  = b[idx];
    }
}

// ---------------- copy pooled features into X0[:, 0:256] ------------------
__global__ void copy_pool(const float* __restrict__ pooled, float* __restrict__ X0)
{
    int idx = blockIdx.x * blockDim.x + threadIdx.x;
    if (idx < NNODES * CPOOL) {
        int n = idx >> 8;
        int c = idx & 255;
        X0[(size_t)n * INDIM + c] = pooled[idx];
    }
}

// ---------------- copy X0 into out[:, 0:384] -------------------------------
__global__ void copy_x0_out(const float* __restrict__ X0, float* __restrict__ out)
{
    int idx = blockIdx.x * blockDim.x + threadIdx.x;
    if (idx < NNODES * INDIM) {
        int n = idx / INDIM;
        int c = idx - n * INDIM;
        out[(size_t)n * OUTLD + c] = X0[idx];
    }
}

// ---------------- edge aggregation: x_new[n] = max_k relu(A[src_k]+C[n]) ---
__global__ void aggregate(const float* __restrict__ D,
                          const int*   __restrict__ src,
                          float* __restrict__ Xn,    // 4096 x 512
                          float* __restrict__ out,   // 4096 x 1920
                          int out_off)
{
    const int n  = blockIdx.x;
    const int f4 = threadIdx.x;   // 0..127

    float4 c = *reinterpret_cast<const float4*>(D + (size_t)n * 1024 + 512 + f4 * 4);
    float4 m = make_float4(0.f, 0.f, 0.f, 0.f);

    #pragma unroll
    for (int k = 0; k < KNBR; k++) {
        int j = src[n * KNBR + k];
        float4 a = *reinterpret_cast<const float4*>(D + (size_t)j * 1024 + f4 * 4);
        m.x = fmaxf(m.x, a.x + c.x);
        m.y = fmaxf(m.y, a.y + c.y);
        m.z = fmaxf(m.z, a.z + c.z);
        m.w = fmaxf(m.w, a.w + c.w);
    }
    *reinterpret_cast<float4*>(Xn  + (size_t)n * LDIM  + f4 * 4) = m;
    *reinterpret_cast<float4*>(out + (size_t)n * OUTLD + out_off + f4 * 4) = m;
}

// ---------------------------------------------------------------------------
extern "C" void kernel_launch(void* const* d_in, const int* in_sizes, int n_in,
                              void* d_out, int out_size)
{
    const float* rois   = (const float*)d_in[0];
    const float* pooled = (const float*)d_in[1];
    const int*   edge   = (const int*)  d_in[2];   // (2, 65536): row 0 = src
    const float* gW1    = (const float*)d_in[3];
    const float* gb1    = (const float*)d_in[4];
    const float* gW2    = (const float*)d_in[5];
    const float* gb2    = (const float*)d_in[6];
    const float* fcW[3] = {(const float*)d_in[7], (const float*)d_in[9],  (const float*)d_in[11]};
    const float* fcb[3] = {(const float*)d_in[8], (const float*)d_in[10], (const float*)d_in[12]};
    float* out = (float*)d_out;

    const int* src = edge;

    float *H, *X0, *X, *D, *Wcat, *biasL;
    cudaGetSymbolAddress((void**)&H,     g_H);
    cudaGetSymbolAddress((void**)&X0,    g_X0);
    cudaGetSymbolAddress((void**)&X,     g_X);
    cudaGetSymbolAddress((void**)&D,     g_D);
    cudaGetSymbolAddress((void**)&Wcat,  g_Wcat);
    cudaGetSymbolAddress((void**)&biasL, g_biasL);

    // 1) geo MLP layer 1: H = relu(rois @ gW1.T + gb1)   (4096x7 -> 4096x128)
    sgemm_tn<<<dim3(GDIM / TN, NNODES / TM), dim3(16, 16)>>>(
        rois, 7, gW1, 7, gb1, H, GDIM, 0, NNODES, GDIM, 7, 1);

    // 2) geo MLP layer 2: X0[:,256:384] = relu(H @ gW2.T + gb2)  (K=128)
    sgemm_f2<<<dim3(GDIM / BN, NNODES / BM), 256>>>(
        H, GDIM, gW2, GDIM, gb2, X0, INDIM, CPOOL, GDIM, 1);

    // 3) X0[:,0:256] = pooled
    copy_pool<<<(NNODES * CPOOL + 255) / 256, 256>>>(pooled, X0);

    // 4) out[:,0:384] = X0
    copy_x0_out<<<(NNODES * INDIM + 255) / 256, 256>>>(X0, out);

    // 5) three EdgeConv layers
    const int Kin[3]    = {INDIM, LDIM, LDIM};
    const int outOff[3] = {384, 384 + 512, 384 + 1024};

    for (int l = 0; l < 3; l++) {
        int k = Kin[l];

        prep_w<<<(512 * k + 255) / 256, 256>>>(fcW[l], fcb[l], k, Wcat, biasL);

        const float* Xin = (l == 0) ? X0 : X;
        int          ldx = (l == 0) ? INDIM : LDIM;
        sgemm_f2<<<dim3(1024 / BN, NNODES / BM), 256>>>(
            Xin, ldx, Wcat, k, biasL, D, 1024, 0, k, 0);

        aggregate<<<NNODES, 128>>>(D, src, X, out, outOff[l]);
    }
}

// round 4
// speedup vs baseline: 5.1389x; 2.2962x over previous
#include <cuda_runtime.h>
#include <cuda_bf16.h>
#include <cstdint>

// Problem constants
#define NNODES 4096       // B*N = 8*512
#define KNBR   16
#define CPOOL  256
#define GDIM   128
#define INDIM  384        // CPOOL + GDIM
#define LDIM   512
#define OUTLD  1920       // 384 + 3*512

// ---------------- device scratch (no allocations allowed) ----------------
__device__ float g_H   [NNODES * GDIM];
__device__ float g_X0  [NNODES * INDIM];
__device__ float g_D   [NNODES * 1024];
__device__ float g_biasL[1024];
__device__ __align__(16) __nv_bfloat16 g_X0h[NNODES * INDIM];
__device__ __align__(16) __nv_bfloat16 g_X0l[NNODES * INDIM];
__device__ __align__(16) __nv_bfloat16 g_Xh [NNODES * LDIM];
__device__ __align__(16) __nv_bfloat16 g_Xl [NNODES * LDIM];
__device__ __align__(16) __nv_bfloat16 g_Wh [1024 * LDIM];
__device__ __align__(16) __nv_bfloat16 g_Wl [1024 * LDIM];

// ======================= helpers =======================
__device__ __forceinline__ uint32_t smem_u32(const void* p) {
    uint32_t a;
    asm("{ .reg .u64 t; cvta.to.shared.u64 t, %1; cvt.u32.u64 %0, t; }"
        : "=r"(a) : "l"(p));
    return a;
}
__device__ __forceinline__ uint32_t sw64(uint32_t o) {   // SW64 swizzle for 64B rows
    return o ^ ((o >> 3) & 0x30);
}
__device__ __forceinline__ void cp16(uint32_t dst, const void* src) {
    asm volatile("cp.async.cg.shared.global [%0], [%1], 16;" :: "r"(dst), "l"(src));
}
#define CP_COMMIT() asm volatile("cp.async.commit_group;" ::: "memory")
#define CP_WAIT(n)  asm volatile("cp.async.wait_group %0;" :: "n"(n) : "memory")

#define LDSM4(r, a) \
    asm volatile("ldmatrix.sync.aligned.m8n8.x4.shared.b16 {%0,%1,%2,%3}, [%4];" \
        : "=r"((r)[0]), "=r"((r)[1]), "=r"((r)[2]), "=r"((r)[3]) : "r"(a))

#define MMA16816(d, a, b0, b1) \
    asm volatile("mma.sync.aligned.m16n8k16.row.col.f32.bf16.bf16.f32 " \
        "{%0,%1,%2,%3}, {%4,%5,%6,%7}, {%8,%9}, {%0,%1,%2,%3};" \
        : "+f"((d)[0]), "+f"((d)[1]), "+f"((d)[2]), "+f"((d)[3]) \
        : "r"((a)[0]), "r"((a)[1]), "r"((a)[2]), "r"((a)[3]), "r"(b0), "r"(b1))

// ======================= mma.sync GEMM =======================
// D(4096 x 1024) = X(4096 x Kin) @ W(1024 x Kin)^T + bias
// bf16 hi/lo split, 3-pass compensation, fp32 accumulation.
// CTA tile 128x128, BK=32, 8 warps (warp tile 32x64), cp.async double buffer.
// smem layout per stage (32KB): Ah | Al | Bh | Bl, each 128 rows x 64B, SW64.
#define ARR_BYTES (128 * 64)                // 8192
#define STG_BYTES (4 * ARR_BYTES)           // 32768
#define GEMM_SMEM (2 * STG_BYTES)           // 65536

__global__ __launch_bounds__(256) void gemm_mma(
    const __nv_bfloat16* __restrict__ Ah, const __nv_bfloat16* __restrict__ Al,
    const __nv_bfloat16* __restrict__ Bh, const __nv_bfloat16* __restrict__ Bl,
    const float* __restrict__ bias,
    float* __restrict__ C,      // ldc = 1024
    int Kin)
{
    extern __shared__ char smem[];
    const uint32_t sb  = smem_u32(smem);
    const int tid  = threadIdx.x;
    const int lane = tid & 31;
    const int wid  = tid >> 5;
    const int bm   = blockIdx.y * 128;
    const int bn   = blockIdx.x * 128;
    const int m0   = (wid & 3) * 32;     // warp m-offset in tile
    const int n0   = (wid >> 2) * 64;    // warp n-offset in tile

    // cp.async chunk mapping: 512 chunks of 16B per array, 2 per thread
    const int r0c = tid >> 2;            // chunk tid:      row 0..63
    const int s0c = tid & 3;             //                 seg 0..3
    const int r1c = (tid + 256) >> 2;    // chunk tid+256:  row 64..127
    const int s1c = s0c;

    const __nv_bfloat16* gsrc[4] = { Ah, Al, Bh, Bl };
    const int grow0[4] = { bm, bm, bn, bn };

    // per-thread smem store offsets (swizzled, stage-relative)
    uint32_t soff0[4], soff1[4];
    #pragma unroll
    for (int a = 0; a < 4; a++) {
        soff0[a] = a * ARR_BYTES + sw64((uint32_t)(r0c * 64 + s0c * 16));
        soff1[a] = a * ARR_BYTES + sw64((uint32_t)(r1c * 64 + s1c * 16));
    }

    const int nk = Kin / 32;

    // ---- issue stage 0 ----
    {
        const uint32_t bufb = sb;
        #pragma unroll
        for (int a = 0; a < 4; a++) {
            cp16(bufb + soff0[a], gsrc[a] + (size_t)(grow0[a] + r0c) * Kin + s0c * 8);
            cp16(bufb + soff1[a], gsrc[a] + (size_t)(grow0[a] + r1c) * Kin + s1c * 8);
        }
        CP_COMMIT();
    }

    float acc[2][8][4];
    #pragma unroll
    for (int i = 0; i < 2; i++)
        #pragma unroll
        for (int j = 0; j < 8; j++)
            #pragma unroll
            for (int q = 0; q < 4; q++)
                acc[i][j][q] = 0.0f;

    // ldmatrix per-lane address components
    const int a_row = lane & 15;             // row within m16 tile
    const int a_kh  = (lane >> 4) & 1;       // k half (0/8)
    const int b_row = ((lane >> 4) << 3) + (lane & 7);  // row within n16 pair
    const int b_kh  = (lane >> 3) & 1;

    for (int s = 0; s < nk; s++) {
        const uint32_t bufb = sb + (uint32_t)(s & 1) * STG_BYTES;

        if (s + 1 < nk) {
            const uint32_t nb = sb + (uint32_t)((s + 1) & 1) * STG_BYTES;
            const int kb = (s + 1) * 32;
            #pragma unroll
            for (int a = 0; a < 4; a++) {
                cp16(nb + soff0[a], gsrc[a] + (size_t)(grow0[a] + r0c) * Kin + kb + s0c * 8);
                cp16(nb + soff1[a], gsrc[a] + (size_t)(grow0[a] + r1c) * Kin + kb + s1c * 8);
            }
            CP_COMMIT();
            CP_WAIT(1);
        } else {
            CP_WAIT(0);
        }
        __syncthreads();

        #pragma unroll
        for (int kk = 0; kk < 2; kk++) {
            uint32_t fah[2][4], fal[2][4];
            #pragma unroll
            for (int mt = 0; mt < 2; mt++) {
                const uint32_t off =
                    sw64((uint32_t)((m0 + mt * 16 + a_row) * 64 + kk * 32 + a_kh * 16));
                LDSM4(fah[mt], bufb + 0 * ARR_BYTES + off);
                LDSM4(fal[mt], bufb + 1 * ARR_BYTES + off);
            }
            uint32_t fbh[4][4], fbl[4][4];
            #pragma unroll
            for (int nt = 0; nt < 4; nt++) {
                const uint32_t off =
                    sw64((uint32_t)((n0 + nt * 16 + b_row) * 64 + kk * 32 + b_kh * 16));
                LDSM4(fbh[nt], bufb + 2 * ARR_BYTES + off);
                LDSM4(fbl[nt], bufb + 3 * ARR_BYTES + off);
            }
            #pragma unroll
            for (int mt = 0; mt < 2; mt++) {
                #pragma unroll
                for (int ni = 0; ni < 8; ni++) {
                    const uint32_t bh0 = fbh[ni >> 1][(ni & 1) * 2];
                    const uint32_t bh1 = fbh[ni >> 1][(ni & 1) * 2 + 1];
                    const uint32_t bl0 = fbl[ni >> 1][(ni & 1) * 2];
                    const uint32_t bl1 = fbl[ni >> 1][(ni & 1) * 2 + 1];
                    MMA16816(acc[mt][ni], fah[mt], bh0, bh1);
                    MMA16816(acc[mt][ni], fah[mt], bl0, bl1);
                    MMA16816(acc[mt][ni], fal[mt], bh0, bh1);
                }
            }
        }
        __syncthreads();
    }

    // ---- epilogue: write D with bias ----
    #pragma unroll
    for (int mt = 0; mt < 2; mt++) {
        const int r = bm + m0 + mt * 16 + (lane >> 2);
        #pragma unroll
        for (int ni = 0; ni < 8; ni++) {
            const int col = bn + n0 + ni * 8 + (lane & 3) * 2;
            const float b0 = bias[col], b1 = bias[col + 1];
            float2 v0 = { acc[mt][ni][0] + b0, acc[mt][ni][1] + b1 };
            float2 v1 = { acc[mt][ni][2] + b0, acc[mt][ni][3] + b1 };
            *(float2*)(C + (size_t)r * 1024 + col)       = v0;
            *(float2*)(C + (size_t)(r + 8) * 1024 + col) = v1;
        }
    }
}

// ---------------- generic tiled SGEMM (K=7 geo layer) ------
#define TM 64
#define TN 64
#define TK 16

__global__ void sgemm_tn(const float* __restrict__ A, int lda,
                         const float* __restrict__ B, int ldb,
                         const float* __restrict__ bias,
                         float* __restrict__ C, int ldc, int c_off,
                         int M, int N, int K, int do_relu)
{
    __shared__ float Ams[TK][TM];
    __shared__ float Bms[TK][TN];

    const int bm = blockIdx.y * TM;
    const int bn = blockIdx.x * TN;
    const int tx = threadIdx.x;
    const int ty = threadIdx.y;
    const int tid = ty * 16 + tx;

    float acc[4][4] = {};

    for (int k0 = 0; k0 < K; k0 += TK) {
        #pragma unroll
        for (int i = tid; i < TM * TK; i += 256) {
            int m = i / TK, k = i % TK;
            float v = 0.0f;
            int gm = bm + m, gk = k0 + k;
            if (gm < M && gk < K) v = A[(size_t)gm * lda + gk];
            Ams[k][m] = v;
        }
        #pragma unroll
        for (int i = tid; i < TN * TK; i += 256) {
            int n = i / TK, k = i % TK;
            float v = 0.0f;
            int gn = bn + n, gk = k0 + k;
            if (gn < N && gk < K) v = B[(size_t)gn * ldb + gk];
            Bms[k][n] = v;
        }
        __syncthreads();

        #pragma unroll
        for (int kk = 0; kk < TK; kk++) {
            float4 av = *reinterpret_cast<const float4*>(&Ams[kk][ty * 4]);
            float4 bv = *reinterpret_cast<const float4*>(&Bms[kk][tx * 4]);
            float a[4] = {av.x, av.y, av.z, av.w};
            float b[4] = {bv.x, bv.y, bv.z, bv.w};
            #pragma unroll
            for (int i = 0; i < 4; i++)
                #pragma unroll
                for (int j = 0; j < 4; j++)
                    acc[i][j] = fmaf(a[i], b[j], acc[i][j]);
        }
        __syncthreads();
    }

    #pragma unroll
    for (int i = 0; i < 4; i++) {
        int m = bm + ty * 4 + i;
        if (m >= M) continue;
        #pragma unroll
        for (int j = 0; j < 4; j++) {
            int n = bn + tx * 4 + j;
            if (n >= N) continue;
            float v = acc[i][j];
            if (bias) v += bias[n];
            if (do_relu) v = fmaxf(v, 0.0f);
            C[(size_t)m * ldc + c_off + n] = v;
        }
    }
}

// ---------------- f32x2 SGEMM (geo layer 2, K=128) ----------------
#define BM 128
#define BN 64
#define BK 16

__global__ __launch_bounds__(256) void sgemm_f2(
    const float* __restrict__ A, int lda,
    const float* __restrict__ B, int ldb,
    const float* __restrict__ bias,
    float* __restrict__ C, int ldc, int c_off,
    int K, int do_relu)
{
    __shared__ float As[2][BK][BM];
    __shared__ float Bs[2][BK][BN];

    const int tid = threadIdx.x;
    const int tx  = tid & 15;
    const int ty  = tid >> 4;
    const int bm  = blockIdx.y * BM;
    const int bn  = blockIdx.x * BN;

    const int am  = tid >> 1;
    const int ak  = (tid & 1) * 8;
    const int bnr = tid >> 2;
    const int bk  = (tid & 3) * 4;

    const float* Aptr = A + (size_t)(bm + am) * lda + ak;
    const float* Bptr = B + (size_t)(bn + bnr) * ldb + bk;

    float4 ra0 = *(const float4*)(Aptr);
    float4 ra1 = *(const float4*)(Aptr + 4);
    float4 rb  = *(const float4*)(Bptr);

    As[0][ak + 0][am] = ra0.x;  As[0][ak + 1][am] = ra0.y;
    As[0][ak + 2][am] = ra0.z;  As[0][ak + 3][am] = ra0.w;
    As[0][ak + 4][am] = ra1.x;  As[0][ak + 5][am] = ra1.y;
    As[0][ak + 6][am] = ra1.z;  As[0][ak + 7][am] = ra1.w;
    Bs[0][bk + 0][bnr] = rb.x;  Bs[0][bk + 1][bnr] = rb.y;
    Bs[0][bk + 2][bnr] = rb.z;  Bs[0][bk + 3][bnr] = rb.w;

    unsigned long long acc[4][4];
    #pragma unroll
    for (int i = 0; i < 4; i++)
        #pragma unroll
        for (int j = 0; j < 4; j++)
            acc[i][j] = 0ull;

    const int nk = K / BK;
    int buf = 0;
    __syncthreads();

    for (int kt = 0; kt < nk; kt++) {
        const bool has_next = (kt + 1 < nk);
        if (has_next) {
            const float* Ap = Aptr + (kt + 1) * BK;
            ra0 = *(const float4*)(Ap);
            ra1 = *(const float4*)(Ap + 4);
            rb  = *(const float4*)(Bptr + (kt + 1) * BK);
        }

        #pragma unroll
        for (int kk = 0; kk < BK; kk++) {
            ulonglong2 av0 = *(const ulonglong2*)&As[buf][kk][ty * 8];
            ulonglong2 av1 = *(const ulonglong2*)&As[buf][kk][ty * 8 + 4];
            unsigned long long a0 = av0.x, a1 = av0.y, a2 = av1.x, a3 = av1.y;

            float4 bq = *(const float4*)&Bs[buf][kk][tx * 4];
            unsigned long long b0, b1, b2, b3;
            asm("mov.b64 %0, {%1, %1};" : "=l"(b0) : "f"(bq.x));
            asm("mov.b64 %0, {%1, %1};" : "=l"(b1) : "f"(bq.y));
            asm("mov.b64 %0, {%1, %1};" : "=l"(b2) : "f"(bq.z));
            asm("mov.b64 %0, {%1, %1};" : "=l"(b3) : "f"(bq.w));

            #define FF2(d, a, b) \
                asm("fma.rn.f32x2 %0, %1, %2, %0;" : "+l"(d) : "l"(a), "l"(b))
            FF2(acc[0][0], a0, b0); FF2(acc[0][1], a0, b1);
            FF2(acc[0][2], a0, b2); FF2(acc[0][3], a0, b3);
            FF2(acc[1][0], a1, b0); FF2(acc[1][1], a1, b1);
            FF2(acc[1][2], a1, b2); FF2(acc[1][3], a1, b3);
            FF2(acc[2][0], a2, b0); FF2(acc[2][1], a2, b1);
            FF2(acc[2][2], a2, b2); FF2(acc[2][3], a2, b3);
            FF2(acc[3][0], a3, b0); FF2(acc[3][1], a3, b1);
            FF2(acc[3][2], a3, b2); FF2(acc[3][3], a3, b3);
            #undef FF2
        }

        if (has_next) {
            const int nb = buf ^ 1;
            As[nb][ak + 0][am] = ra0.x;  As[nb][ak + 1][am] = ra0.y;
            As[nb][ak + 2][am] = ra0.z;  As[nb][ak + 3][am] = ra0.w;
            As[nb][ak + 4][am] = ra1.x;  As[nb][ak + 5][am] = ra1.y;
            As[nb][ak + 6][am] = ra1.z;  As[nb][ak + 7][am] = ra1.w;
            Bs[nb][bk + 0][bnr] = rb.x;  Bs[nb][bk + 1][bnr] = rb.y;
            Bs[nb][bk + 2][bnr] = rb.z;  Bs[nb][bk + 3][bnr] = rb.w;
            __syncthreads();
            buf = nb;
        }
    }

    #pragma unroll
    for (int mp = 0; mp < 4; mp++) {
        const int r0 = bm + ty * 8 + mp * 2;
        #pragma unroll
        for (int j = 0; j < 4; j++) {
            const int n = bn + tx * 4 + j;
            float lo, hi;
            asm("mov.b64 {%0, %1}, %2;" : "=f"(lo), "=f"(hi) : "l"(acc[mp][j]));
            float bv = bias ? bias[n] : 0.0f;
            lo += bv; hi += bv;
            if (do_relu) { lo = fmaxf(lo, 0.0f); hi = fmaxf(hi, 0.0f); }
            C[(size_t)r0 * ldc + c_off + n]       = lo;
            C[(size_t)(r0 + 1) * ldc + c_off + n] = hi;
        }
    }
}

// ---------------- weight prep: bf16 hi/lo of [W_l ; W_r - W_l] ------------
__global__ void prep_w(const float* __restrict__ W,  // 512 x (2*Kin)
                       const float* __restrict__ b,  // 512
                       int Kin,
                       __nv_bfloat16* __restrict__ Wh,
                       __nv_bfloat16* __restrict__ Wl,
                       float* __restrict__ biasL)
{
    int idx = blockIdx.x * blockDim.x + threadIdx.x;
    int total = 512 * Kin;
    if (idx < total) {
        int r = idx / Kin, c = idx % Kin;
        float wl = W[(size_t)r * 2 * Kin + c];
        float wr = W[(size_t)r * 2 * Kin + Kin + c];
        float d  = wr - wl;

        __nv_bfloat16 h0 = __float2bfloat16(wl);
        Wh[(size_t)r * Kin + c] = h0;
        Wl[(size_t)r * Kin + c] = __float2bfloat16(wl - __bfloat162float(h0));
        __nv_bfloat16 h1 = __float2bfloat16(d);
        Wh[(size_t)(512 + r) * Kin + c] = h1;
        Wl[(size_t)(512 + r) * Kin + c] = __float2bfloat16(d - __bfloat162float(h1));
    }
    if (idx < 512) {
        biasL[idx]       = 0.0f;
        biasL[512 + idx] = b[idx];
    }
}

// ---------------- split fp32 -> bf16 hi/lo --------------------------------
__global__ void convert_split(const float* __restrict__ x,
                              __nv_bfloat16* __restrict__ h,
                              __nv_bfloat16* __restrict__ l, int n)
{
    int i = blockIdx.x * blockDim.x + threadIdx.x;
    if (i < n) {
        float v = x[i];
        __nv_bfloat16 hb = __float2bfloat16(v);
        h[i] = hb;
        l[i] = __float2bfloat16(v - __bfloat162float(hb));
    }
}

// ---------------- copy pooled features into X0[:, 0:256] ------------------
__global__ void copy_pool(const float* __restrict__ pooled, float* __restrict__ X0)
{
    int idx = blockIdx.x * blockDim.x + threadIdx.x;
    if (idx < NNODES * CPOOL) {
        int n = idx >> 8;
        int c = idx & 255;
        X0[(size_t)n * INDIM + c] = pooled[idx];
    }
}

// ---------------- copy X0 into out[:, 0:384] -------------------------------
__global__ void copy_x0_out(const float* __restrict__ X0, float* __restrict__ out)
{
    int idx = blockIdx.x * blockDim.x + threadIdx.x;
    if (idx < NNODES * INDIM) {
        int n = idx / INDIM;
        int c = idx - n * INDIM;
        out[(size_t)n * OUTLD + c] = X0[idx];
    }
}

// ---------------- aggregation + bf16 split of the new features ------------
__global__ void aggregate(const float* __restrict__ D,
                          const int*   __restrict__ src,
                          __nv_bfloat16* __restrict__ Xh,  // 4096 x 512
                          __nv_bfloat16* __restrict__ Xl,
                          float* __restrict__ out,         // 4096 x 1920
                          int out_off)
{
    const int n  = blockIdx.x;
    const int f4 = threadIdx.x;   // 0..127

    float4 c = *reinterpret_cast<const float4*>(D + (size_t)n * 1024 + 512 + f4 * 4);
    float4 m = make_float4(0.f, 0.f, 0.f, 0.f);

    #pragma unroll
    for (int k = 0; k < KNBR; k++) {
        int j = src[n * KNBR + k];
        float4 a = *reinterpret_cast<const float4*>(D + (size_t)j * 1024 + f4 * 4);
        m.x = fmaxf(m.x, a.x + c.x);
        m.y = fmaxf(m.y, a.y + c.y);
        m.z = fmaxf(m.z, a.z + c.z);
        m.w = fmaxf(m.w, a.w + c.w);
    }
    *reinterpret_cast<float4*>(out + (size_t)n * OUTLD + out_off + f4 * 4) = m;

    __nv_bfloat16 hx = __float2bfloat16(m.x), hy = __float2bfloat16(m.y);
    __nv_bfloat16 hz = __float2bfloat16(m.z), hw = __float2bfloat16(m.w);
    __nv_bfloat162 h01, h23, l01, l23;
    h01.x = hx; h01.y = hy; h23.x = hz; h23.y = hw;
    l01.x = __float2bfloat16(m.x - __bfloat162float(hx));
    l01.y = __float2bfloat16(m.y - __bfloat162float(hy));
    l23.x = __float2bfloat16(m.z - __bfloat162float(hz));
    l23.y = __float2bfloat16(m.w - __bfloat162float(hw));

    *reinterpret_cast<__nv_bfloat162*>(Xh + (size_t)n * LDIM + f4 * 4)     = h01;
    *reinterpret_cast<__nv_bfloat162*>(Xh + (size_t)n * LDIM + f4 * 4 + 2) = h23;
    *reinterpret_cast<__nv_bfloat162*>(Xl + (size_t)n * LDIM + f4 * 4)     = l01;
    *reinterpret_cast<__nv_bfloat162*>(Xl + (size_t)n * LDIM + f4 * 4 + 2) = l23;
}

// ---------------------------------------------------------------------------
extern "C" void kernel_launch(void* const* d_in, const int* in_sizes, int n_in,
                              void* d_out, int out_size)
{
    const float* rois   = (const float*)d_in[0];
    const float* pooled = (const float*)d_in[1];
    const int*   edge   = (const int*)  d_in[2];   // (2, 65536): row 0 = src
    const float* gW1    = (const float*)d_in[3];
    const float* gb1    = (const float*)d_in[4];
    const float* gW2    = (const float*)d_in[5];
    const float* gb2    = (const float*)d_in[6];
    const float* fcW[3] = {(const float*)d_in[7], (const float*)d_in[9],  (const float*)d_in[11]};
    const float* fcb[3] = {(const float*)d_in[8], (const float*)d_in[10], (const float*)d_in[12]};
    float* out = (float*)d_out;

    const int* src = edge;

    float *H, *X0, *D, *biasL;
    __nv_bfloat16 *X0h, *X0l, *Xh, *Xl, *Wh, *Wl;
    cudaGetSymbolAddress((void**)&H,     g_H);
    cudaGetSymbolAddress((void**)&X0,    g_X0);
    cudaGetSymbolAddress((void**)&D,     g_D);
    cudaGetSymbolAddress((void**)&biasL, g_biasL);
    cudaGetSymbolAddress((void**)&X0h,   g_X0h);
    cudaGetSymbolAddress((void**)&X0l,   g_X0l);
    cudaGetSymbolAddress((void**)&Xh,    g_Xh);
    cudaGetSymbolAddress((void**)&Xl,    g_Xl);
    cudaGetSymbolAddress((void**)&Wh,    g_Wh);
    cudaGetSymbolAddress((void**)&Wl,    g_Wl);

    cudaFuncSetAttribute(gemm_mma, cudaFuncAttributeMaxDynamicSharedMemorySize, GEMM_SMEM);

    // 1) geo MLP layer 1: H = relu(rois @ gW1.T + gb1)
    sgemm_tn<<<dim3(GDIM / TN, NNODES / TM), dim3(16, 16)>>>(
        rois, 7, gW1, 7, gb1, H, GDIM, 0, NNODES, GDIM, 7, 1);

    // 2) geo MLP layer 2: X0[:,256:384] = relu(H @ gW2.T + gb2)
    sgemm_f2<<<dim3(GDIM / BN, NNODES / BM), 256>>>(
        H, GDIM, gW2, GDIM, gb2, X0, INDIM, CPOOL, GDIM, 1);

    // 3) X0[:,0:256] = pooled
    copy_pool<<<(NNODES * CPOOL + 255) / 256, 256>>>(pooled, X0);

    // 4) out[:,0:384] = X0
    copy_x0_out<<<(NNODES * INDIM + 255) / 256, 256>>>(X0, out);

    // 5) bf16 split of X0
    convert_split<<<(NNODES * INDIM + 255) / 256, 256>>>(X0, X0h, X0l, NNODES * INDIM);

    // 6) three EdgeConv layers on mma.sync tensor cores
    const int Kin[3]    = {INDIM, LDIM, LDIM};
    const int outOff[3] = {384, 384 + 512, 384 + 1024};

    for (int l = 0; l < 3; l++) {
        int k = Kin[l];

        prep_w<<<(512 * k + 255) / 256, 256>>>(fcW[l], fcb[l], k, Wh, Wl, biasL);

        const __nv_bfloat16* Ah = (l == 0) ? X0h : Xh;
        const __nv_bfloat16* Al = (l == 0) ? X0l : Xl;
        gemm_mma<<<dim3(1024 / 128, NNODES / 128), 256, GEMM_SMEM>>>(
            Ah, Al, Wh, Wl, biasL, D, k);

        aggregate<<<NNODES, 128>>>(D, src, Xh, Xl, out, outOff[l]);
    }
}